// round 3
// baseline (speedup 1.0000x reference)
#include <cuda_runtime.h>
#include <cstdint>

// ---------------- problem constants ----------------
#define B_    8
#define C_    1024
#define H_    48
#define P_    (H_*H_)        // 2304 positions per image
#define HP_   24             // pooled spatial
#define P2_   (HP_*HP_)      // 576
#define POS4_ (P2_*P2_)      // 331776 = 24^4
#define EPS_L2 1e-6f
#define EPS_MM 1e-5f

// ---------------- scratch (device globals; no allocation allowed) ----------------
__device__ float g_faN[B_*C_*P_];       // 75.5 MB  normalized A, [b][c][p]
__device__ float g_fbN[B_*C_*P_];       // 75.5 MB  normalized B, [b][c][p]
__device__ float g_corr[B_*P_*P_];      // 170 MB   relu+normalized correlation [b][p][q]
__device__ float g_pool[B_*P2_*P2_];    // 10.6 MB  pooled [b][p2][q2]
__device__ float g_amax[B_*P2_];
__device__ float g_bmax[B_*P2_];
__device__ float g_c1[B_*10*POS4_];     // 106 MB
__device__ float g_c2[B_*10*POS4_];     // 106 MB
__device__ float g_x3[B_*POS4_];        // 10.6 MB

// ---------------- 1) channel L2 norm ----------------
// f: [B, C, P] -> out same layout, normalized over C per (b, p).
// block (32 p, 8 c-slices); coalesced across p.
__global__ void l2norm_kernel(const float* __restrict__ f, float* __restrict__ o) {
    int tx = threadIdx.x, ty = threadIdx.y;
    int p  = blockIdx.x * 32 + tx;
    int b  = blockIdx.y;
    const float* src = f + (size_t)b * C_ * P_ + p;
    float s = 0.f;
    for (int c = ty; c < C_; c += 8) {
        float v = src[(size_t)c * P_];
        s += v * v;
    }
    __shared__ float red[8][33];
    __shared__ float inv[32];
    red[ty][tx] = s;
    __syncthreads();
    if (ty == 0) {
        float t = 0.f;
        #pragma unroll
        for (int r = 0; r < 8; r++) t += red[r][tx];
        inv[tx] = rsqrtf(t + EPS_L2);
    }
    __syncthreads();
    float iv = inv[tx];
    float* dst = o + (size_t)b * C_ * P_ + p;
    for (int c = ty; c < C_; c += 8)
        dst[(size_t)c * P_] = src[(size_t)c * P_] * iv;
}

// ---------------- 2) correlation GEMM, fused relu + feature-norm epilogue ----------------
// C[p][q] = sum_c A[c][p] * B[c][q]  per batch. Both operands K-outer (coalesced tiles).
#define BM 128
#define BN 128
#define BK 16
__global__ void __launch_bounds__(256) corr_gemm_kernel(const float* __restrict__ A,
                                                        const float* __restrict__ Bm,
                                                        float* __restrict__ Co) {
    int b = blockIdx.z;
    const float* Ab = A  + (size_t)b * C_ * P_;
    const float* Bb = Bm + (size_t)b * C_ * P_;
    float*       Cb = Co + (size_t)b * P_ * P_;
    int pBase = blockIdx.y * BM;
    int qBase = blockIdx.x * BN;

    __shared__ float As[BK][BM];
    __shared__ float Bs[BK][BN];

    int tid = threadIdx.x;
    int tx = tid & 15;          // 0..15  -> q microtile
    int ty = tid >> 4;          // 0..15  -> p microtile
    int lr = tid >> 5;          // 0..7   load row
    int lc = (tid & 31) * 4;    // load col (float4)

    float acc[8][8];
    #pragma unroll
    for (int i = 0; i < 8; i++)
        #pragma unroll
        for (int j = 0; j < 8; j++) acc[i][j] = 0.f;

    for (int k0 = 0; k0 < C_; k0 += BK) {
        #pragma unroll
        for (int r = 0; r < BK; r += 8) {
            float4 va = *(const float4*)(Ab + (size_t)(k0 + lr + r) * P_ + pBase + lc);
            *(float4*)(&As[lr + r][lc]) = va;
            float4 vb = *(const float4*)(Bb + (size_t)(k0 + lr + r) * P_ + qBase + lc);
            *(float4*)(&Bs[lr + r][lc]) = vb;
        }
        __syncthreads();
        #pragma unroll
        for (int k = 0; k < BK; k++) {
            float ra[8], rb[8];
            *(float4*)(ra)     = *(float4*)(&As[k][ty * 8]);
            *(float4*)(ra + 4) = *(float4*)(&As[k][ty * 8 + 4]);
            *(float4*)(rb)     = *(float4*)(&Bs[k][tx * 8]);
            *(float4*)(rb + 4) = *(float4*)(&Bs[k][tx * 8 + 4]);
            #pragma unroll
            for (int i = 0; i < 8; i++)
                #pragma unroll
                for (int j = 0; j < 8; j++)
                    acc[i][j] += ra[i] * rb[j];
        }
        __syncthreads();
    }
    // epilogue: relu then x / sqrt(x^2 + eps), vectorized stores
    #pragma unroll
    for (int i = 0; i < 8; i++) {
        int p = pBase + ty * 8 + i;
        float* row = Cb + (size_t)p * P_ + qBase + tx * 8;
        float4 o0, o1;
        float tmp[8];
        #pragma unroll
        for (int j = 0; j < 8; j++) {
            float v = acc[i][j];
            v = v > 0.f ? v : 0.f;
            tmp[j] = v * rsqrtf(v * v + EPS_L2);
        }
        o0 = make_float4(tmp[0], tmp[1], tmp[2], tmp[3]);
        o1 = make_float4(tmp[4], tmp[5], tmp[6], tmp[7]);
        *(float4*)(row)     = o0;
        *(float4*)(row + 4) = o1;
    }
}

// ---------------- 3) 4D max pool k=2 ----------------
__global__ void maxpool_kernel(const float* __restrict__ c, float* __restrict__ out) {
    int idx = blockIdx.x * 256 + threadIdx.x;
    const int N = B_ * POS4_;
    if (idx >= N) return;
    int l = idx % HP_;       int t = idx / HP_;
    int k = t % HP_;         t /= HP_;
    int j = t % HP_;         t /= HP_;
    int i = t % HP_;         int b = t / HP_;
    const float* base = c + (size_t)b * P_ * P_;
    float m = 0.f;   // values are >= 0 after relu
    #pragma unroll
    for (int di = 0; di < 2; di++)
        #pragma unroll
        for (int dj = 0; dj < 2; dj++) {
            int p = (2 * i + di) * H_ + 2 * j + dj;
            const float* row = base + (size_t)p * P_;
            #pragma unroll
            for (int dk = 0; dk < 2; dk++)
                #pragma unroll
                for (int dl = 0; dl < 2; dl++)
                    m = fmaxf(m, row[(2 * k + dk) * H_ + 2 * l + dl]);
        }
    out[idx] = m;
}

// ---------------- 4) mutual matching helpers ----------------
// rowmax: amax[b][p2] = max_q2 x[b][p2][q2].  One warp per row.
__global__ void rowmax_kernel(const float* __restrict__ x, float* __restrict__ out) {
    int row = blockIdx.x * 8 + threadIdx.y;           // rows = B_*P2_ = 4608
    const float* r = x + (size_t)row * P2_;
    float m = -1e30f;
    for (int q = threadIdx.x; q < P2_; q += 32) m = fmaxf(m, r[q]);
    #pragma unroll
    for (int o = 16; o; o >>= 1) m = fmaxf(m, __shfl_xor_sync(0xffffffffu, m, o));
    if (threadIdx.x == 0) out[row] = m;
}

// colmax: bmax[b][q2] = max_p2 x[b][p2][q2].
__global__ void colmax_kernel(const float* __restrict__ x, float* __restrict__ out) {
    int b = blockIdx.y;
    int q = blockIdx.x * 64 + threadIdx.x;
    const float* base = x + (size_t)b * P2_ * P2_ + q;
    float m = -1e30f;
    #pragma unroll 8
    for (int p = 0; p < P2_; p++) m = fmaxf(m, base[(size_t)p * P2_]);
    out[b * P2_ + q] = m;
}

// elementwise: out = c * (c/(amax+e)) * (c/(bmax+e))
__global__ void mm_kernel(const float* __restrict__ x, const float* __restrict__ amax,
                          const float* __restrict__ bmax, float* __restrict__ out) {
    int idx = blockIdx.x * 256 + threadIdx.x;
    const int N = B_ * POS4_;
    if (idx >= N) return;
    int q2 = idx % P2_;
    int t  = idx / P2_;
    int p2 = t % P2_;
    int b  = t / P2_;
    float v  = x[idx];
    float t1 = v / (amax[b * P2_ + p2] + EPS_MM);
    float t2 = v / (bmax[b * P2_ + q2] + EPS_MM);
    out[idx] = v * t1 * t2;
}

// ---------------- 5) conv4d (3x3x3x3, SAME, +bias, +relu) ----------------
// x: [B, CIN, 24,24,24,24]  w: [COUT, CIN, 3,3,3,3]  y: [B, COUT, 24,24,24,24]
// block = one (b, i, j); threads (24 l, 6 k-groups), each thread does 4 k outputs.
template<int CIN, int COUT>
__global__ void __launch_bounds__(144) conv4d_kernel(const float* __restrict__ x,
                                                     const float* __restrict__ w,
                                                     const float* __restrict__ bias,
                                                     float* __restrict__ y) {
    int b  = blockIdx.y;
    int ij = blockIdx.x;
    int i = ij / HP_, j = ij % HP_;
    int tx = threadIdx.x;              // l: 0..23
    int ty = threadIdx.y;              // k group: 0..5
    int tid = ty * 24 + tx;
    int k0 = ty * 4;

    __shared__ float sw[COUT * CIN * 81];
    __shared__ float sx[26][27];

    for (int idx = tid; idx < COUT * CIN * 81; idx += 144) sw[idx] = w[idx];

    float acc[COUT][4];
    #pragma unroll
    for (int co = 0; co < COUT; co++) {
        float bv = bias[co];
        #pragma unroll
        for (int kk = 0; kk < 4; kk++) acc[co][kk] = bv;
    }

    for (int ci = 0; ci < CIN; ci++) {
        const float* xc = x + (size_t)(b * CIN + ci) * POS4_;
        #pragma unroll
        for (int di = 0; di < 3; di++) {
            int ii = i + di - 1;
            #pragma unroll
            for (int dj = 0; dj < 3; dj++) {
                int jj = j + dj - 1;
                __syncthreads();   // protect previous slab consumption (and sw on iter 0)
                bool valid = (ii >= 0) && (ii < HP_) && (jj >= 0) && (jj < HP_);
                const float* plane = xc + (size_t)(ii * HP_ + jj) * P2_;
                for (int idx = tid; idx < 26 * 26; idx += 144) {
                    int kk = idx / 26, ll = idx % 26;
                    int ks = kk - 1, ls = ll - 1;
                    float v = 0.f;
                    if (valid && ks >= 0 && ks < HP_ && ls >= 0 && ls < HP_)
                        v = plane[ks * HP_ + ls];
                    sx[kk][ll] = v;
                }
                __syncthreads();
                float xr[6][3];
                #pragma unroll
                for (int r = 0; r < 6; r++)
                    #pragma unroll
                    for (int c2 = 0; c2 < 3; c2++)
                        xr[r][c2] = sx[k0 + r][tx + c2];
                #pragma unroll
                for (int co = 0; co < COUT; co++) {
                    const float* wp = &sw[((co * CIN + ci) * 9 + di * 3 + dj) * 9];
                    float wr[9];
                    #pragma unroll
                    for (int t = 0; t < 9; t++) wr[t] = wp[t];
                    #pragma unroll
                    for (int kk = 0; kk < 4; kk++)
                        #pragma unroll
                        for (int dk = 0; dk < 3; dk++)
                            #pragma unroll
                            for (int dl = 0; dl < 3; dl++)
                                acc[co][kk] += xr[kk + dk][dl] * wr[dk * 3 + dl];
                }
            }
        }
    }
    size_t posbase = (size_t)(i * HP_ + j) * P2_ + tx;
    #pragma unroll
    for (int co = 0; co < COUT; co++) {
        float* yo = y + (size_t)(b * COUT + co) * POS4_ + posbase;
        #pragma unroll
        for (int kk = 0; kk < 4; kk++) {
            float v = acc[co][kk];
            yo[(k0 + kk) * HP_] = v > 0.f ? v : 0.f;
        }
    }
}

// ---------------- launch ----------------
extern "C" void kernel_launch(void* const* d_in, const int* in_sizes, int n_in,
                              void* d_out, int out_size) {
    const float* fA = (const float*)d_in[0];
    const float* fB = (const float*)d_in[1];
    const float* w1 = (const float*)d_in[2];
    const float* b1 = (const float*)d_in[3];
    const float* w2 = (const float*)d_in[4];
    const float* b2 = (const float*)d_in[5];
    const float* w3 = (const float*)d_in[6];
    const float* b3 = (const float*)d_in[7];
    float* out = (float*)d_out;

    float *faN, *fbN, *corr, *pool, *amax, *bmax, *c1, *c2, *x3;
    cudaGetSymbolAddress((void**)&faN,  g_faN);
    cudaGetSymbolAddress((void**)&fbN,  g_fbN);
    cudaGetSymbolAddress((void**)&corr, g_corr);
    cudaGetSymbolAddress((void**)&pool, g_pool);
    cudaGetSymbolAddress((void**)&amax, g_amax);
    cudaGetSymbolAddress((void**)&bmax, g_bmax);
    cudaGetSymbolAddress((void**)&c1,   g_c1);
    cudaGetSymbolAddress((void**)&c2,   g_c2);
    cudaGetSymbolAddress((void**)&x3,   g_x3);

    // 1) normalize
    dim3 nb(P_ / 32, B_), nt(32, 8);
    l2norm_kernel<<<nb, nt>>>(fA, faN);
    l2norm_kernel<<<nb, nt>>>(fB, fbN);

    // 2) correlation + relu + feature-norm
    corr_gemm_kernel<<<dim3(P_ / BN, P_ / BM, B_), 256>>>(faN, fbN, corr);

    // 3) 4D maxpool
    const int NP = B_ * POS4_;
    maxpool_kernel<<<(NP + 255) / 256, 256>>>(corr, pool);

    // 4) mutual matching (in place)
    rowmax_kernel<<<(B_ * P2_) / 8, dim3(32, 8)>>>(pool, amax);
    colmax_kernel<<<dim3(P2_ / 64, B_), 64>>>(pool, bmax);
    mm_kernel<<<(NP + 255) / 256, 256>>>(pool, amax, bmax, pool);

    // 5) neighbourhood consensus convs
    dim3 cg(P2_, B_), cb(24, 6);
    conv4d_kernel<1, 10><<<cg, cb>>>(pool, w1, b1, c1);
    conv4d_kernel<10, 10><<<cg, cb>>>(c1, w2, b2, c2);
    conv4d_kernel<10, 1><<<cg, cb>>>(c2, w3, b3, x3);

    // 6) final mutual matching -> output
    rowmax_kernel<<<(B_ * P2_) / 8, dim3(32, 8)>>>(x3, amax);
    colmax_kernel<<<dim3(P2_ / 64, B_), 64>>>(x3, bmax);
    mm_kernel<<<(NP + 255) / 256, 256>>>(x3, amax, bmax, out);
}

// round 8
// speedup vs baseline: 1.2251x; 1.2251x over previous
#include <cuda_runtime.h>
#include <cuda_bf16.h>
#include <cstdint>

// ---------------- problem constants ----------------
#define B_    8
#define C_    1024
#define H_    48
#define P_    (H_*H_)        // 2304
#define HP_   24
#define P2_   (HP_*HP_)      // 576
#define POS4_ (P2_*P2_)      // 331776
#define EPS_L2 1e-6f
#define EPS_MM 1e-5f

// ---------------- scratch (device globals) ----------------
__device__ __nv_bfloat16 g_faH[B_*P_*C_];   // A hi, [b][p][c] K-major
__device__ __nv_bfloat16 g_faL[B_*P_*C_];
__device__ __nv_bfloat16 g_fbH[B_*P_*C_];
__device__ __nv_bfloat16 g_fbL[B_*P_*C_];
__device__ float g_corr[B_*P_*P_];
__device__ float g_pool[B_*P2_*P2_];
__device__ float g_amax[B_*P2_];
__device__ float g_bmax[B_*P2_];
__device__ float g_c1[B_*10*POS4_];
__device__ float g_c2[B_*10*POS4_];
__device__ float g_x3[B_*POS4_];

// ---------------- PTX helpers ----------------
__device__ __forceinline__ uint32_t smem_u32(const void* p) {
    uint32_t a;
    asm("{ .reg .u64 t; cvta.to.shared.u64 t, %1; cvt.u32.u64 %0, t; }" : "=r"(a) : "l"(p));
    return a;
}
__device__ __forceinline__ void ldsm_x4(uint32_t* r, uint32_t addr) {
    asm volatile("ldmatrix.sync.aligned.m8n8.x4.shared.b16 {%0,%1,%2,%3}, [%4];"
        : "=r"(r[0]), "=r"(r[1]), "=r"(r[2]), "=r"(r[3]) : "r"(addr));
}
__device__ __forceinline__ void mma_bf16(float* d, const uint32_t* a, uint32_t b0, uint32_t b1) {
    asm volatile("mma.sync.aligned.m16n8k16.row.col.f32.bf16.bf16.f32 "
        "{%0,%1,%2,%3}, {%4,%5,%6,%7}, {%8,%9}, {%0,%1,%2,%3};"
        : "+f"(d[0]), "+f"(d[1]), "+f"(d[2]), "+f"(d[3])
        : "r"(a[0]), "r"(a[1]), "r"(a[2]), "r"(a[3]), "r"(b0), "r"(b1));
}
__device__ __forceinline__ void cp16(uint32_t sdst, const void* g) {
    asm volatile("cp.async.cg.shared.global [%0], [%1], 16;" :: "r"(sdst), "l"(g));
}
#define CP_COMMIT() asm volatile("cp.async.commit_group;" ::: "memory")
#define CP_WAIT(n)  asm volatile("cp.async.wait_group %0;" :: "n"(n) : "memory")

// packed fp32x2
__device__ __forceinline__ unsigned long long pk2(float lo, float hi) {
    unsigned long long r; asm("mov.b64 %0, {%1, %2};" : "=l"(r) : "f"(lo), "f"(hi)); return r;
}
__device__ __forceinline__ float2 upk2(unsigned long long v) {
    float2 r; asm("mov.b64 {%0, %1}, %2;" : "=f"(r.x), "=f"(r.y) : "l"(v)); return r;
}
__device__ __forceinline__ void ffma2(unsigned long long& d, unsigned long long a, unsigned long long b) {
    asm("fma.rn.f32x2 %0, %1, %2, %0;" : "+l"(d) : "l"(a), "l"(b));
}

// ---------------- 1) L2 norm + transpose + hi/lo bf16 split ----------------
__global__ void l2norm_split(const float* __restrict__ f,
                             __nv_bfloat16* __restrict__ oh,
                             __nv_bfloat16* __restrict__ ol) {
    int tx = threadIdx.x, ty = threadIdx.y;   // (32, 8)
    int p0 = blockIdx.x * 32;
    int b  = blockIdx.y;
    const float* src = f + (size_t)b * C_ * P_;
    float s = 0.f;
    for (int c = ty; c < C_; c += 8) {
        float v = src[(size_t)c * P_ + p0 + tx];
        s += v * v;
    }
    __shared__ float red[8][33];
    __shared__ float inv[32];
    red[ty][tx] = s;
    __syncthreads();
    if (ty == 0) {
        float t = 0.f;
        #pragma unroll
        for (int r = 0; r < 8; r++) t += red[r][tx];
        inv[tx] = rsqrtf(t + EPS_L2);
    }
    __shared__ float tile[32][33];
    __nv_bfloat16* ohb = oh + (size_t)b * P_ * C_;
    __nv_bfloat16* olb = ol + (size_t)b * P_ * C_;
    for (int c0 = 0; c0 < C_; c0 += 32) {
        __syncthreads();
        #pragma unroll
        for (int r = 0; r < 4; r++) {
            int c = c0 + ty + r * 8;
            tile[ty + r * 8][tx] = src[(size_t)c * P_ + p0 + tx];
        }
        __syncthreads();
        #pragma unroll
        for (int r = 0; r < 4; r++) {
            int pl = ty + r * 8;
            float v = tile[tx][pl] * inv[pl];
            __nv_bfloat16 h = __float2bfloat16_rn(v);
            float lo = v - __bfloat162float(h);
            size_t o = (size_t)(p0 + pl) * C_ + c0 + tx;
            ohb[o] = h;
            olb[o] = __float2bfloat16_rn(lo);
        }
    }
}

// ---------------- 2) correlation GEMM via mma.sync (bf16 hi/lo split) ----------------
// corr[p][q] = sum_c a[p][c]*b[q][c]; fused relu + x*rsqrt(x^2+eps).
// CTA 128x128, 256 threads, warp tile 32x64. K chunk 32, cp.async double buffer.
#define KCH   32
#define NCHNK (C_ / KCH)          // 32
#define ROWB  80                  // 64B data + 16B pad -> conflict-free ldmatrix
#define OPB   (128 * ROWB)        // 10240 per operand tile
#define STAGE (4 * OPB)           // Ah, Al, Bh, Bl
#define DYNSM (2 * STAGE)         // 81920

__global__ void __launch_bounds__(256) corr_gemm_mma(
    const __nv_bfloat16* __restrict__ AH, const __nv_bfloat16* __restrict__ AL,
    const __nv_bfloat16* __restrict__ BH, const __nv_bfloat16* __restrict__ BL,
    float* __restrict__ Co) {
    extern __shared__ __align__(128) char dynsm[];
    uint32_t sb = smem_u32(dynsm);

    int b = blockIdx.z;
    int pBase = blockIdx.y * 128;
    int qBase = blockIdx.x * 128;

    int tid  = threadIdx.x;
    int lane = tid & 31;
    int wid  = tid >> 5;
    int mBase = (wid & 3) * 32;
    int nBase = (wid >> 2) * 64;

    // ---- load mapping: op = tid&3 (Ah,Al,Bh,Bl), rows r and r+64, 4x16B per row
    int op = tid & 3;
    int lr = tid >> 2;             // 0..63
    const __nv_bfloat16* gb;
    if (op == 0)      gb = AH + ((size_t)b * P_ + pBase) * C_;
    else if (op == 1) gb = AL + ((size_t)b * P_ + pBase) * C_;
    else if (op == 2) gb = BH + ((size_t)b * P_ + qBase) * C_;
    else              gb = BL + ((size_t)b * P_ + qBase) * C_;
    // byte-based row pointers (row stride C_ bf16 = 2*C_ bytes)
    const char* gRow0 = (const char*)gb + (size_t)lr * (C_ * 2);
    const char* gRow1 = (const char*)gb + (size_t)(lr + 64) * (C_ * 2);
    uint32_t sOpBase = sb + op * OPB;

    float acc[2][8][4];
    #pragma unroll
    for (int mi = 0; mi < 2; mi++)
        #pragma unroll
        for (int ni = 0; ni < 8; ni++)
            #pragma unroll
            for (int e = 0; e < 4; e++) acc[mi][ni][e] = 0.f;

    // ---- ldmatrix address components
    uint32_t aOff = (uint32_t)((mBase + (lane & 15)) * ROWB + (lane >> 4) * 16);
    uint32_t bOff = (uint32_t)((nBase + (lane & 7) + ((lane >> 4) << 3)) * ROWB + ((lane >> 3) & 1) * 16);

    // ---- prologue: chunk 0 -> buf 0
    {
        uint32_t s0 = sOpBase + lr * ROWB;
        uint32_t s1 = sOpBase + (lr + 64) * ROWB;
        #pragma unroll
        for (int c = 0; c < 4; c++) { cp16(s0 + c * 16, gRow0 + c * 16); cp16(s1 + c * 16, gRow1 + c * 16); }
        CP_COMMIT();
    }

    for (int s = 0; s < NCHNK; s++) {
        int buf = s & 1;
        if (s + 1 < NCHNK) {
            int nb = (s + 1) & 1;
            size_t byteOff = (size_t)(s + 1) * (KCH * 2);   // chunk offset in BYTES
            const char* g0 = gRow0 + byteOff;
            const char* g1 = gRow1 + byteOff;
            uint32_t s0 = sOpBase + nb * STAGE + lr * ROWB;
            uint32_t s1 = sOpBase + nb * STAGE + (lr + 64) * ROWB;
            #pragma unroll
            for (int c = 0; c < 4; c++) { cp16(s0 + c * 16, g0 + c * 16); cp16(s1 + c * 16, g1 + c * 16); }
            CP_COMMIT();
            CP_WAIT(1);
        } else {
            CP_WAIT(0);
        }
        __syncthreads();

        uint32_t stg = sb + buf * STAGE;
        #pragma unroll
        for (int ks = 0; ks < 2; ks++) {
            uint32_t ah[2][4], al[2][4], bh[4][4], bl[4][4];
            #pragma unroll
            for (int mi = 0; mi < 2; mi++) {
                uint32_t ao = stg + aOff + mi * 16 * ROWB + ks * 32;
                ldsm_x4(ah[mi], ao);
                ldsm_x4(al[mi], ao + OPB);
            }
            #pragma unroll
            for (int ni = 0; ni < 4; ni++) {
                uint32_t bo = stg + 2 * OPB + bOff + ni * 16 * ROWB + ks * 32;
                ldsm_x4(bh[ni], bo);
                ldsm_x4(bl[ni], bo + OPB);
            }
            #pragma unroll
            for (int mi = 0; mi < 2; mi++)
                #pragma unroll
                for (int ni = 0; ni < 4; ni++)
                    #pragma unroll
                    for (int h = 0; h < 2; h++) {
                        float* a8 = acc[mi][ni * 2 + h];
                        mma_bf16(a8, ah[mi], bh[ni][h * 2], bh[ni][h * 2 + 1]);
                        mma_bf16(a8, ah[mi], bl[ni][h * 2], bl[ni][h * 2 + 1]);
                        mma_bf16(a8, al[mi], bh[ni][h * 2], bh[ni][h * 2 + 1]);
                    }
        }
        __syncthreads();
    }

    // ---- epilogue: relu + x*rsqrt(x^2+eps), float2 stores
    float* Cb = Co + (size_t)b * P_ * P_;
    #pragma unroll
    for (int mi = 0; mi < 2; mi++) {
        int r0 = pBase + mBase + mi * 16 + (lane >> 2);
        #pragma unroll
        for (int ni = 0; ni < 8; ni++) {
            int c0 = qBase + nBase + ni * 8 + (lane & 3) * 2;
            float v0 = acc[mi][ni][0], v1 = acc[mi][ni][1];
            float v2 = acc[mi][ni][2], v3 = acc[mi][ni][3];
            v0 = v0 > 0.f ? v0 : 0.f;  v1 = v1 > 0.f ? v1 : 0.f;
            v2 = v2 > 0.f ? v2 : 0.f;  v3 = v3 > 0.f ? v3 : 0.f;
            float2 o0 = make_float2(v0 * rsqrtf(v0 * v0 + EPS_L2), v1 * rsqrtf(v1 * v1 + EPS_L2));
            float2 o1 = make_float2(v2 * rsqrtf(v2 * v2 + EPS_L2), v3 * rsqrtf(v3 * v3 + EPS_L2));
            *(float2*)(Cb + (size_t)r0 * P_ + c0)       = o0;
            *(float2*)(Cb + (size_t)(r0 + 8) * P_ + c0) = o1;
        }
    }
}

// ---------------- 3) 4D max pool k=2 ----------------
__global__ void maxpool_kernel(const float* __restrict__ c, float* __restrict__ out) {
    int idx = blockIdx.x * 256 + threadIdx.x;
    const int N = B_ * POS4_;
    if (idx >= N) return;
    int l = idx % HP_;       int t = idx / HP_;
    int k = t % HP_;         t /= HP_;
    int j = t % HP_;         t /= HP_;
    int i = t % HP_;         int b = t / HP_;
    const float* base = c + (size_t)b * P_ * P_;
    float m = 0.f;
    #pragma unroll
    for (int di = 0; di < 2; di++)
        #pragma unroll
        for (int dj = 0; dj < 2; dj++) {
            int p = (2 * i + di) * H_ + 2 * j + dj;
            const float* row = base + (size_t)p * P_;
            #pragma unroll
            for (int dk = 0; dk < 2; dk++)
                #pragma unroll
                for (int dl = 0; dl < 2; dl++)
                    m = fmaxf(m, row[(2 * k + dk) * H_ + 2 * l + dl]);
        }
    out[idx] = m;
}

// ---------------- 4) mutual matching helpers ----------------
__global__ void rowmax_kernel(const float* __restrict__ x, float* __restrict__ out) {
    int row = blockIdx.x * 8 + threadIdx.y;
    const float* r = x + (size_t)row * P2_;
    float m = -1e30f;
    for (int q = threadIdx.x; q < P2_; q += 32) m = fmaxf(m, r[q]);
    #pragma unroll
    for (int o = 16; o; o >>= 1) m = fmaxf(m, __shfl_xor_sync(0xffffffffu, m, o));
    if (threadIdx.x == 0) out[row] = m;
}
__global__ void colmax_kernel(const float* __restrict__ x, float* __restrict__ out) {
    int b = blockIdx.y;
    int q = blockIdx.x * 64 + threadIdx.x;
    const float* base = x + (size_t)b * P2_ * P2_ + q;
    float m = -1e30f;
    #pragma unroll 8
    for (int p = 0; p < P2_; p++) m = fmaxf(m, base[(size_t)p * P2_]);
    out[b * P2_ + q] = m;
}
__global__ void mm_kernel(const float* __restrict__ x, const float* __restrict__ amax,
                          const float* __restrict__ bmax, float* __restrict__ out) {
    int idx = blockIdx.x * 256 + threadIdx.x;
    const int N = B_ * POS4_;
    if (idx >= N) return;
    int q2 = idx % P2_;
    int t  = idx / P2_;
    int p2 = t % P2_;
    int b  = t / P2_;
    float v  = x[idx];
    float t1 = v / (amax[b * P2_ + p2] + EPS_MM);
    float t2 = v / (bmax[b * P2_ + q2] + EPS_MM);
    out[idx] = v * t1 * t2;
}

// ---------------- 5a) conv4d with packed-f32x2 over output-channel pairs ----------------
template<int CIN, int COUT>
__global__ void __launch_bounds__(144) conv4d_pk(const float* __restrict__ x,
                                                 const float* __restrict__ w,
                                                 const float* __restrict__ bias,
                                                 float* __restrict__ y) {
    static_assert(COUT % 2 == 0, "COUT must be even");
    constexpr int CO2 = COUT / 2;
    int b  = blockIdx.y;
    int ij = blockIdx.x;
    int i = ij / HP_, j = ij % HP_;
    int tx = threadIdx.x;              // l: 0..23
    int ty = threadIdx.y;              // k group: 0..5
    int tid = ty * 24 + tx;
    int k0 = ty * 4;

    __shared__ unsigned long long swp[CO2 * CIN * 81];
    __shared__ float sx[26][27];

    for (int idx = tid; idx < CO2 * CIN * 81; idx += 144) {
        int co2 = idx / (CIN * 81), r = idx % (CIN * 81);
        swp[idx] = pk2(w[(2 * co2) * CIN * 81 + r], w[(2 * co2 + 1) * CIN * 81 + r]);
    }

    unsigned long long acc2[CO2][4];
    #pragma unroll
    for (int co2 = 0; co2 < CO2; co2++) {
        unsigned long long bv = pk2(bias[2 * co2], bias[2 * co2 + 1]);
        #pragma unroll
        for (int kk = 0; kk < 4; kk++) acc2[co2][kk] = bv;
    }

    for (int ci = 0; ci < CIN; ci++) {
        const float* xc = x + (size_t)(b * CIN + ci) * POS4_;
        #pragma unroll
        for (int di = 0; di < 3; di++) {
            int ii = i + di - 1;
            #pragma unroll
            for (int dj = 0; dj < 3; dj++) {
                int jj = j + dj - 1;
                __syncthreads();
                bool valid = (ii >= 0) && (ii < HP_) && (jj >= 0) && (jj < HP_);
                const float* plane = xc + (size_t)(ii * HP_ + jj) * P2_;
                for (int idx = tid; idx < 26 * 26; idx += 144) {
                    int kk = idx / 26, ll = idx % 26;
                    int ks = kk - 1, ls = ll - 1;
                    float v = 0.f;
                    if (valid && ks >= 0 && ks < HP_ && ls >= 0 && ls < HP_)
                        v = plane[ks * HP_ + ls];
                    sx[kk][ll] = v;
                }
                __syncthreads();
                unsigned long long xp[6][3];
                #pragma unroll
                for (int r = 0; r < 6; r++)
                    #pragma unroll
                    for (int c2 = 0; c2 < 3; c2++) {
                        float v = sx[k0 + r][tx + c2];
                        xp[r][c2] = pk2(v, v);
                    }
                #pragma unroll
                for (int co2 = 0; co2 < CO2; co2++) {
                    const unsigned long long* wpp = &swp[((co2 * CIN + ci) * 9 + di * 3 + dj) * 9];
                    unsigned long long wr[9];
                    #pragma unroll
                    for (int t = 0; t < 9; t++) wr[t] = wpp[t];
                    #pragma unroll
                    for (int kk = 0; kk < 4; kk++)
                        #pragma unroll
                        for (int dk = 0; dk < 3; dk++)
                            #pragma unroll
                            for (int dl = 0; dl < 3; dl++)
                                ffma2(acc2[co2][kk], xp[kk + dk][dl], wr[dk * 3 + dl]);
                }
            }
        }
    }
    size_t posbase = (size_t)(i * HP_ + j) * P2_ + tx;
    #pragma unroll
    for (int co2 = 0; co2 < CO2; co2++) {
        float* y0 = y + (size_t)(b * COUT + 2 * co2) * POS4_ + posbase;
        float* y1 = y0 + POS4_;
        #pragma unroll
        for (int kk = 0; kk < 4; kk++) {
            float2 pr = upk2(acc2[co2][kk]);
            y0[(k0 + kk) * HP_] = pr.x > 0.f ? pr.x : 0.f;
            y1[(k0 + kk) * HP_] = pr.y > 0.f ? pr.y : 0.f;
        }
    }
}

// ---------------- 5b) scalar conv4d (COUT==1) ----------------
template<int CIN, int COUT>
__global__ void __launch_bounds__(144) conv4d_kernel(const float* __restrict__ x,
                                                     const float* __restrict__ w,
                                                     const float* __restrict__ bias,
                                                     float* __restrict__ y) {
    int b  = blockIdx.y;
    int ij = blockIdx.x;
    int i = ij / HP_, j = ij % HP_;
    int tx = threadIdx.x;
    int ty = threadIdx.y;
    int tid = ty * 24 + tx;
    int k0 = ty * 4;

    __shared__ float sw[COUT * CIN * 81];
    __shared__ float sx[26][27];

    for (int idx = tid; idx < COUT * CIN * 81; idx += 144) sw[idx] = w[idx];

    float acc[COUT][4];
    #pragma unroll
    for (int co = 0; co < COUT; co++) {
        float bv = bias[co];
        #pragma unroll
        for (int kk = 0; kk < 4; kk++) acc[co][kk] = bv;
    }

    for (int ci = 0; ci < CIN; ci++) {
        const float* xc = x + (size_t)(b * CIN + ci) * POS4_;
        #pragma unroll
        for (int di = 0; di < 3; di++) {
            int ii = i + di - 1;
            #pragma unroll
            for (int dj = 0; dj < 3; dj++) {
                int jj = j + dj - 1;
                __syncthreads();
                bool valid = (ii >= 0) && (ii < HP_) && (jj >= 0) && (jj < HP_);
                const float* plane = xc + (size_t)(ii * HP_ + jj) * P2_;
                for (int idx = tid; idx < 26 * 26; idx += 144) {
                    int kk = idx / 26, ll = idx % 26;
                    int ks = kk - 1, ls = ll - 1;
                    float v = 0.f;
                    if (valid && ks >= 0 && ks < HP_ && ls >= 0 && ls < HP_)
                        v = plane[ks * HP_ + ls];
                    sx[kk][ll] = v;
                }
                __syncthreads();
                float xr[6][3];
                #pragma unroll
                for (int r = 0; r < 6; r++)
                    #pragma unroll
                    for (int c2 = 0; c2 < 3; c2++)
                        xr[r][c2] = sx[k0 + r][tx + c2];
                #pragma unroll
                for (int co = 0; co < COUT; co++) {
                    const float* wp = &sw[((co * CIN + ci) * 9 + di * 3 + dj) * 9];
                    float wr[9];
                    #pragma unroll
                    for (int t = 0; t < 9; t++) wr[t] = wp[t];
                    #pragma unroll
                    for (int kk = 0; kk < 4; kk++)
                        #pragma unroll
                        for (int dk = 0; dk < 3; dk++)
                            #pragma unroll
                            for (int dl = 0; dl < 3; dl++)
                                acc[co][kk] += xr[kk + dk][dl] * wr[dk * 3 + dl];
                }
            }
        }
    }
    size_t posbase = (size_t)(i * HP_ + j) * P2_ + tx;
    #pragma unroll
    for (int co = 0; co < COUT; co++) {
        float* yo = y + (size_t)(b * COUT + co) * POS4_ + posbase;
        #pragma unroll
        for (int kk = 0; kk < 4; kk++) {
            float v = acc[co][kk];
            yo[(k0 + kk) * HP_] = v > 0.f ? v : 0.f;
        }
    }
}

// ---------------- launch ----------------
extern "C" void kernel_launch(void* const* d_in, const int* in_sizes, int n_in,
                              void* d_out, int out_size) {
    const float* fA = (const float*)d_in[0];
    const float* fB = (const float*)d_in[1];
    const float* w1 = (const float*)d_in[2];
    const float* b1 = (const float*)d_in[3];
    const float* w2 = (const float*)d_in[4];
    const float* b2 = (const float*)d_in[5];
    const float* w3 = (const float*)d_in[6];
    const float* b3 = (const float*)d_in[7];
    float* out = (float*)d_out;

    __nv_bfloat16 *faH, *faL, *fbH, *fbL;
    float *corr, *pool, *amax, *bmax, *c1, *c2, *x3;
    cudaGetSymbolAddress((void**)&faH,  g_faH);
    cudaGetSymbolAddress((void**)&faL,  g_faL);
    cudaGetSymbolAddress((void**)&fbH,  g_fbH);
    cudaGetSymbolAddress((void**)&fbL,  g_fbL);
    cudaGetSymbolAddress((void**)&corr, g_corr);
    cudaGetSymbolAddress((void**)&pool, g_pool);
    cudaGetSymbolAddress((void**)&amax, g_amax);
    cudaGetSymbolAddress((void**)&bmax, g_bmax);
    cudaGetSymbolAddress((void**)&c1,   g_c1);
    cudaGetSymbolAddress((void**)&c2,   g_c2);
    cudaGetSymbolAddress((void**)&x3,   g_x3);

    // 1) normalize + transpose + split
    dim3 nb(P_ / 32, B_), nt(32, 8);
    l2norm_split<<<nb, nt>>>(fA, faH, faL);
    l2norm_split<<<nb, nt>>>(fB, fbH, fbL);

    // 2) correlation on mma.sync tensor cores
    cudaFuncSetAttribute(corr_gemm_mma, cudaFuncAttributeMaxDynamicSharedMemorySize, DYNSM);
    corr_gemm_mma<<<dim3(P_ / 128, P_ / 128, B_), 256, DYNSM>>>(faH, faL, fbH, fbL, corr);

    // 3) 4D maxpool
    const int NP = B_ * POS4_;
    maxpool_kernel<<<(NP + 255) / 256, 256>>>(corr, pool);

    // 4) mutual matching (in place)
    rowmax_kernel<<<(B_ * P2_) / 8, dim3(32, 8)>>>(pool, amax);
    colmax_kernel<<<dim3(P2_ / 64, B_), 64>>>(pool, bmax);
    mm_kernel<<<(NP + 255) / 256, 256>>>(pool, amax, bmax, pool);

    // 5) neighbourhood consensus convs
    dim3 cg(P2_, B_), cb(24, 6);
    conv4d_pk<1, 10><<<cg, cb>>>(pool, w1, b1, c1);
    conv4d_pk<10, 10><<<cg, cb>>>(c1, w2, b2, c2);
    conv4d_kernel<10, 1><<<cg, cb>>>(c2, w3, b3, x3);

    // 6) final mutual matching -> output
    rowmax_kernel<<<(B_ * P2_) / 8, dim3(32, 8)>>>(x3, amax);
    colmax_kernel<<<dim3(P2_ / 64, B_), 64>>>(x3, bmax);
    mm_kernel<<<(NP + 255) / 256, 256>>>(x3, amax, bmax, out);
}

// round 12
// speedup vs baseline: 1.5158x; 1.2373x over previous
#include <cuda_runtime.h>
#include <cuda_fp16.h>
#include <cstdint>

// ---------------- problem constants ----------------
#define B_    8
#define C_    1024
#define H_    48
#define P_    (H_*H_)        // 2304
#define HP_   24
#define P2_   (HP_*HP_)      // 576
#define POS4_ (P2_*P2_)      // 331776
#define EPS_L2 1e-6f
#define EPS_MM 1e-5f

// ---------------- scratch (device globals) ----------------
__device__ __half g_faN[B_*P_*C_];   // normalized A, fp16, [b][p][c] K-major
__device__ __half g_fbN[B_*P_*C_];   // normalized B, fp16
__device__ float g_corr[B_*P_*P_];
__device__ float g_pool[B_*P2_*P2_];
__device__ float g_amax[B_*P2_];
__device__ float g_bmax[B_*P2_];
__device__ float g_c1[B_*10*POS4_];
__device__ float g_c2[B_*10*POS4_];
__device__ float g_x3[B_*POS4_];

// ---------------- PTX helpers ----------------
__device__ __forceinline__ uint32_t smem_u32(const void* p) {
    uint32_t a;
    asm("{ .reg .u64 t; cvta.to.shared.u64 t, %1; cvt.u32.u64 %0, t; }" : "=r"(a) : "l"(p));
    return a;
}
__device__ __forceinline__ void ldsm_x4(uint32_t* r, uint32_t addr) {
    asm volatile("ldmatrix.sync.aligned.m8n8.x4.shared.b16 {%0,%1,%2,%3}, [%4];"
        : "=r"(r[0]), "=r"(r[1]), "=r"(r[2]), "=r"(r[3]) : "r"(addr));
}
__device__ __forceinline__ void mma_f16(float* d, const uint32_t* a, uint32_t b0, uint32_t b1) {
    asm volatile("mma.sync.aligned.m16n8k16.row.col.f32.f16.f16.f32 "
        "{%0,%1,%2,%3}, {%4,%5,%6,%7}, {%8,%9}, {%0,%1,%2,%3};"
        : "+f"(d[0]), "+f"(d[1]), "+f"(d[2]), "+f"(d[3])
        : "r"(a[0]), "r"(a[1]), "r"(a[2]), "r"(a[3]), "r"(b0), "r"(b1));
}
__device__ __forceinline__ void cp16(uint32_t sdst, const void* g) {
    asm volatile("cp.async.cg.shared.global [%0], [%1], 16;" :: "r"(sdst), "l"(g));
}
#define CP_COMMIT() asm volatile("cp.async.commit_group;" ::: "memory")
#define CP_WAIT(n)  asm volatile("cp.async.wait_group %0;" :: "n"(n) : "memory")

// packed fp32x2
__device__ __forceinline__ unsigned long long pk2(float lo, float hi) {
    unsigned long long r; asm("mov.b64 %0, {%1, %2};" : "=l"(r) : "f"(lo), "f"(hi)); return r;
}
__device__ __forceinline__ float2 upk2(unsigned long long v) {
    float2 r; asm("mov.b64 {%0, %1}, %2;" : "=f"(r.x), "=f"(r.y) : "l"(v)); return r;
}
__device__ __forceinline__ void ffma2(unsigned long long& d, unsigned long long a, unsigned long long b) {
    asm("fma.rn.f32x2 %0, %1, %2, %0;" : "+l"(d) : "l"(a), "l"(b));
}

// ---------------- 1) L2 norm + transpose -> fp16 K-major ----------------
__global__ void l2norm_half(const float* __restrict__ f, __half* __restrict__ o) {
    int tx = threadIdx.x, ty = threadIdx.y;   // (32, 8)
    int p0 = blockIdx.x * 32;
    int b  = blockIdx.y;
    const float* src = f + (size_t)b * C_ * P_;
    float s = 0.f;
    for (int c = ty; c < C_; c += 8) {
        float v = src[(size_t)c * P_ + p0 + tx];
        s += v * v;
    }
    __shared__ float red[8][33];
    __shared__ float inv[32];
    red[ty][tx] = s;
    __syncthreads();
    if (ty == 0) {
        float t = 0.f;
        #pragma unroll
        for (int r = 0; r < 8; r++) t += red[r][tx];
        inv[tx] = rsqrtf(t + EPS_L2);
    }
    __shared__ float tile[32][33];
    __half* ob = o + (size_t)b * P_ * C_;
    for (int c0 = 0; c0 < C_; c0 += 32) {
        __syncthreads();
        #pragma unroll
        for (int r = 0; r < 4; r++) {
            int c = c0 + ty + r * 8;
            tile[ty + r * 8][tx] = src[(size_t)c * P_ + p0 + tx];
        }
        __syncthreads();
        #pragma unroll
        for (int r = 0; r < 4; r++) {
            int pl = ty + r * 8;
            float v = tile[tx][pl] * inv[pl];
            ob[(size_t)(p0 + pl) * C_ + c0 + tx] = __float2half_rn(v);
        }
    }
}

// ---------------- 2) correlation GEMM via mma.sync fp16 ----------------
// corr[p][q] = sum_c a[p][c]*b[q][c]; fused relu + x*rsqrt(x^2+eps).
// CTA 128x128, 256 threads, warp tile 32x64. K chunk 32, cp.async double buffer.
#define KCH   32
#define NCHNK (C_ / KCH)          // 32
#define ROWB  80                  // 64B data + 16B pad -> conflict-free ldmatrix
#define OPB   (128 * ROWB)        // 10240 per operand tile
#define STAGE (2 * OPB)           // A, B
#define DYNSM (2 * STAGE)         // 40960 -> 2 CTAs/SM

__global__ void __launch_bounds__(256) corr_gemm_mma(
    const __half* __restrict__ A, const __half* __restrict__ B,
    float* __restrict__ Co) {
    extern __shared__ __align__(128) char dynsm[];
    uint32_t sb = smem_u32(dynsm);

    int b = blockIdx.z;
    int pBase = blockIdx.y * 128;
    int qBase = blockIdx.x * 128;

    int tid  = threadIdx.x;
    int lane = tid & 31;
    int wid  = tid >> 5;
    int mBase = (wid & 3) * 32;
    int nBase = (wid >> 2) * 64;

    // ---- load mapping: op = tid&1 (A or B), row lr = tid>>1 (0..127), 4x16B per chunk row
    int op = tid & 1;
    int lr = tid >> 1;
    const __half* gb = op ? (B + ((size_t)b * P_ + qBase) * C_)
                          : (A + ((size_t)b * P_ + pBase) * C_);
    const char* gRow = (const char*)gb + (size_t)lr * (C_ * 2);
    uint32_t sOpBase = sb + op * OPB;

    float acc[2][8][4];
    #pragma unroll
    for (int mi = 0; mi < 2; mi++)
        #pragma unroll
        for (int ni = 0; ni < 8; ni++)
            #pragma unroll
            for (int e = 0; e < 4; e++) acc[mi][ni][e] = 0.f;

    // ---- ldmatrix address components (verified mapping from R8)
    uint32_t aOff = (uint32_t)((mBase + (lane & 15)) * ROWB + (lane >> 4) * 16);
    uint32_t bOff = (uint32_t)((nBase + (lane & 7) + ((lane >> 4) << 3)) * ROWB + ((lane >> 3) & 1) * 16);

    // ---- prologue: chunk 0 -> buf 0
    {
        uint32_t s0 = sOpBase + lr * ROWB;
        #pragma unroll
        for (int c = 0; c < 4; c++) cp16(s0 + c * 16, gRow + c * 16);
        CP_COMMIT();
    }

    for (int s = 0; s < NCHNK; s++) {
        int buf = s & 1;
        if (s + 1 < NCHNK) {
            int nb = (s + 1) & 1;
            const char* g0 = gRow + (size_t)(s + 1) * (KCH * 2);   // bytes
            uint32_t s0 = sOpBase + nb * STAGE + lr * ROWB;
            #pragma unroll
            for (int c = 0; c < 4; c++) cp16(s0 + c * 16, g0 + c * 16);
            CP_COMMIT();
            CP_WAIT(1);
        } else {
            CP_WAIT(0);
        }
        __syncthreads();

        uint32_t stg = sb + buf * STAGE;
        #pragma unroll
        for (int ks = 0; ks < 2; ks++) {
            uint32_t ah[2][4], bh[4][4];
            #pragma unroll
            for (int mi = 0; mi < 2; mi++)
                ldsm_x4(ah[mi], stg + aOff + mi * 16 * ROWB + ks * 32);
            #pragma unroll
            for (int ni = 0; ni < 4; ni++)
                ldsm_x4(bh[ni], stg + OPB + bOff + ni * 16 * ROWB + ks * 32);
            #pragma unroll
            for (int mi = 0; mi < 2; mi++)
                #pragma unroll
                for (int ni = 0; ni < 4; ni++)
                    #pragma unroll
                    for (int h = 0; h < 2; h++)
                        mma_f16(acc[mi][ni * 2 + h], ah[mi], bh[ni][h * 2], bh[ni][h * 2 + 1]);
        }
        __syncthreads();
    }

    // ---- epilogue: relu + x*rsqrt(x^2+eps), float2 stores
    float* Cb = Co + (size_t)b * P_ * P_;
    #pragma unroll
    for (int mi = 0; mi < 2; mi++) {
        int r0 = pBase + mBase + mi * 16 + (lane >> 2);
        #pragma unroll
        for (int ni = 0; ni < 8; ni++) {
            int c0 = qBase + nBase + ni * 8 + (lane & 3) * 2;
            float v0 = acc[mi][ni][0], v1 = acc[mi][ni][1];
            float v2 = acc[mi][ni][2], v3 = acc[mi][ni][3];
            v0 = v0 > 0.f ? v0 : 0.f;  v1 = v1 > 0.f ? v1 : 0.f;
            v2 = v2 > 0.f ? v2 : 0.f;  v3 = v3 > 0.f ? v3 : 0.f;
            float2 o0 = make_float2(v0 * rsqrtf(v0 * v0 + EPS_L2), v1 * rsqrtf(v1 * v1 + EPS_L2));
            float2 o1 = make_float2(v2 * rsqrtf(v2 * v2 + EPS_L2), v3 * rsqrtf(v3 * v3 + EPS_L2));
            *(float2*)(Cb + (size_t)r0 * P_ + c0)       = o0;
            *(float2*)(Cb + (size_t)(r0 + 8) * P_ + c0) = o1;
        }
    }
}

// ---------------- 3) 4D max pool k=2 ----------------
__global__ void maxpool_kernel(const float* __restrict__ c, float* __restrict__ out) {
    int idx = blockIdx.x * 256 + threadIdx.x;
    const int N = B_ * POS4_;
    if (idx >= N) return;
    int l = idx % HP_;       int t = idx / HP_;
    int k = t % HP_;         t /= HP_;
    int j = t % HP_;         t /= HP_;
    int i = t % HP_;         int b = t / HP_;
    const float* base = c + (size_t)b * P_ * P_;
    float m = 0.f;
    #pragma unroll
    for (int di = 0; di < 2; di++)
        #pragma unroll
        for (int dj = 0; dj < 2; dj++) {
            int p = (2 * i + di) * H_ + 2 * j + dj;
            const float* row = base + (size_t)p * P_;
            #pragma unroll
            for (int dk = 0; dk < 2; dk++)
                #pragma unroll
                for (int dl = 0; dl < 2; dl++)
                    m = fmaxf(m, row[(2 * k + dk) * H_ + 2 * l + dl]);
        }
    out[idx] = m;
}

// ---------------- 4) mutual matching helpers ----------------
__global__ void rowmax_kernel(const float* __restrict__ x, float* __restrict__ out) {
    int row = blockIdx.x * 8 + threadIdx.y;
    const float* r = x + (size_t)row * P2_;
    float m = -1e30f;
    for (int q = threadIdx.x; q < P2_; q += 32) m = fmaxf(m, r[q]);
    #pragma unroll
    for (int o = 16; o; o >>= 1) m = fmaxf(m, __shfl_xor_sync(0xffffffffu, m, o));
    if (threadIdx.x == 0) out[row] = m;
}
__global__ void colmax_kernel(const float* __restrict__ x, float* __restrict__ out) {
    int b = blockIdx.y;
    int q = blockIdx.x * 64 + threadIdx.x;
    const float* base = x + (size_t)b * P2_ * P2_ + q;
    float m = -1e30f;
    #pragma unroll 8
    for (int p = 0; p < P2_; p++) m = fmaxf(m, base[(size_t)p * P2_]);
    out[b * P2_ + q] = m;
}
__global__ void mm_kernel(const float* __restrict__ x, const float* __restrict__ amax,
                          const float* __restrict__ bmax, float* __restrict__ out) {
    int idx = blockIdx.x * 256 + threadIdx.x;
    const int N = B_ * POS4_;
    if (idx >= N) return;
    int q2 = idx % P2_;
    int t  = idx / P2_;
    int p2 = t % P2_;
    int b  = t / P2_;
    float v  = x[idx];
    float t1 = v / (amax[b * P2_ + p2] + EPS_MM);
    float t2 = v / (bmax[b * P2_ + q2] + EPS_MM);
    out[idx] = v * t1 * t2;
}

// ---------------- 5a) conv4d with packed-f32x2 over output-channel pairs ----------------
template<int CIN, int COUT>
__global__ void __launch_bounds__(144) conv4d_pk(const float* __restrict__ x,
                                                 const float* __restrict__ w,
                                                 const float* __restrict__ bias,
                                                 float* __restrict__ y) {
    static_assert(COUT % 2 == 0, "COUT must be even");
    constexpr int CO2 = COUT / 2;
    int b  = blockIdx.y;
    int ij = blockIdx.x;
    int i = ij / HP_, j = ij % HP_;
    int tx = threadIdx.x;              // l: 0..23
    int ty = threadIdx.y;              // k group: 0..5
    int tid = ty * 24 + tx;
    int k0 = ty * 4;

    __shared__ unsigned long long swp[CO2 * CIN * 81];
    __shared__ float sx[26][27];

    for (int idx = tid; idx < CO2 * CIN * 81; idx += 144) {
        int co2 = idx / (CIN * 81), r = idx % (CIN * 81);
        swp[idx] = pk2(w[(2 * co2) * CIN * 81 + r], w[(2 * co2 + 1) * CIN * 81 + r]);
    }

    unsigned long long acc2[CO2][4];
    #pragma unroll
    for (int co2 = 0; co2 < CO2; co2++) {
        unsigned long long bv = pk2(bias[2 * co2], bias[2 * co2 + 1]);
        #pragma unroll
        for (int kk = 0; kk < 4; kk++) acc2[co2][kk] = bv;
    }

    for (int ci = 0; ci < CIN; ci++) {
        const float* xc = x + (size_t)(b * CIN + ci) * POS4_;
        #pragma unroll
        for (int di = 0; di < 3; di++) {
            int ii = i + di - 1;
            #pragma unroll
            for (int dj = 0; dj < 3; dj++) {
                int jj = j + dj - 1;
                __syncthreads();
                bool valid = (ii >= 0) && (ii < HP_) && (jj >= 0) && (jj < HP_);
                const float* plane = xc + (size_t)(ii * HP_ + jj) * P2_;
                for (int idx = tid; idx < 26 * 26; idx += 144) {
                    int kk = idx / 26, ll = idx % 26;
                    int ks = kk - 1, ls = ll - 1;
                    float v = 0.f;
                    if (valid && ks >= 0 && ks < HP_ && ls >= 0 && ls < HP_)
                        v = plane[ks * HP_ + ls];
                    sx[kk][ll] = v;
                }
                __syncthreads();
                unsigned long long xp[6][3];
                #pragma unroll
                for (int r = 0; r < 6; r++)
                    #pragma unroll
                    for (int c2 = 0; c2 < 3; c2++) {
                        float v = sx[k0 + r][tx + c2];
                        xp[r][c2] = pk2(v, v);
                    }
                #pragma unroll
                for (int co2 = 0; co2 < CO2; co2++) {
                    const unsigned long long* wpp = &swp[((co2 * CIN + ci) * 9 + di * 3 + dj) * 9];
                    unsigned long long wr[9];
                    #pragma unroll
                    for (int t = 0; t < 9; t++) wr[t] = wpp[t];
                    #pragma unroll
                    for (int kk = 0; kk < 4; kk++)
                        #pragma unroll
                        for (int dk = 0; dk < 3; dk++)
                            #pragma unroll
                            for (int dl = 0; dl < 3; dl++)
                                ffma2(acc2[co2][kk], xp[kk + dk][dl], wr[dk * 3 + dl]);
                }
            }
        }
    }
    size_t posbase = (size_t)(i * HP_ + j) * P2_ + tx;
    #pragma unroll
    for (int co2 = 0; co2 < CO2; co2++) {
        float* y0 = y + (size_t)(b * COUT + 2 * co2) * POS4_ + posbase;
        float* y1 = y0 + POS4_;
        #pragma unroll
        for (int kk = 0; kk < 4; kk++) {
            float2 pr = upk2(acc2[co2][kk]);
            y0[(k0 + kk) * HP_] = pr.x > 0.f ? pr.x : 0.f;
            y1[(k0 + kk) * HP_] = pr.y > 0.f ? pr.y : 0.f;
        }
    }
}

// ---------------- 5b) scalar conv4d (COUT==1) ----------------
template<int CIN, int COUT>
__global__ void __launch_bounds__(144) conv4d_kernel(const float* __restrict__ x,
                                                     const float* __restrict__ w,
                                                     const float* __restrict__ bias,
                                                     float* __restrict__ y) {
    int b  = blockIdx.y;
    int ij = blockIdx.x;
    int i = ij / HP_, j = ij % HP_;
    int tx = threadIdx.x;
    int ty = threadIdx.y;
    int tid = ty * 24 + tx;
    int k0 = ty * 4;

    __shared__ float sw[COUT * CIN * 81];
    __shared__ float sx[26][27];

    for (int idx = tid; idx < COUT * CIN * 81; idx += 144) sw[idx] = w[idx];

    float acc[COUT][4];
    #pragma unroll
    for (int co = 0; co < COUT; co++) {
        float bv = bias[co];
        #pragma unroll
        for (int kk = 0; kk < 4; kk++) acc[co][kk] = bv;
    }

    for (int ci = 0; ci < CIN; ci++) {
        const float* xc = x + (size_t)(b * CIN + ci) * POS4_;
        #pragma unroll
        for (int di = 0; di < 3; di++) {
            int ii = i + di - 1;
            #pragma unroll
            for (int dj = 0; dj < 3; dj++) {
                int jj = j + dj - 1;
                __syncthreads();
                bool valid = (ii >= 0) && (ii < HP_) && (jj >= 0) && (jj < HP_);
                const float* plane = xc + (size_t)(ii * HP_ + jj) * P2_;
                for (int idx = tid; idx < 26 * 26; idx += 144) {
                    int kk = idx / 26, ll = idx % 26;
                    int ks = kk - 1, ls = ll - 1;
                    float v = 0.f;
                    if (valid && ks >= 0 && ks < HP_ && ls >= 0 && ls < HP_)
                        v = plane[ks * HP_ + ls];
                    sx[kk][ll] = v;
                }
                __syncthreads();
                float xr[6][3];
                #pragma unroll
                for (int r = 0; r < 6; r++)
                    #pragma unroll
                    for (int c2 = 0; c2 < 3; c2++)
                        xr[r][c2] = sx[k0 + r][tx + c2];
                #pragma unroll
                for (int co = 0; co < COUT; co++) {
                    const float* wp = &sw[((co * CIN + ci) * 9 + di * 3 + dj) * 9];
                    float wr[9];
                    #pragma unroll
                    for (int t = 0; t < 9; t++) wr[t] = wp[t];
                    #pragma unroll
                    for (int kk = 0; kk < 4; kk++)
                        #pragma unroll
                        for (int dk = 0; dk < 3; dk++)
                            #pragma unroll
                            for (int dl = 0; dl < 3; dl++)
                                acc[co][kk] += xr[kk + dk][dl] * wr[dk * 3 + dl];
                }
            }
        }
    }
    size_t posbase = (size_t)(i * HP_ + j) * P2_ + tx;
    #pragma unroll
    for (int co = 0; co < COUT; co++) {
        float* yo = y + (size_t)(b * COUT + co) * POS4_ + posbase;
        #pragma unroll
        for (int kk = 0; kk < 4; kk++) {
            float v = acc[co][kk];
            yo[(k0 + kk) * HP_] = v > 0.f ? v : 0.f;
        }
    }
}

// ---------------- launch ----------------
extern "C" void kernel_launch(void* const* d_in, const int* in_sizes, int n_in,
                              void* d_out, int out_size) {
    const float* fA = (const float*)d_in[0];
    const float* fB = (const float*)d_in[1];
    const float* w1 = (const float*)d_in[2];
    const float* b1 = (const float*)d_in[3];
    const float* w2 = (const float*)d_in[4];
    const float* b2 = (const float*)d_in[5];
    const float* w3 = (const float*)d_in[6];
    const float* b3 = (const float*)d_in[7];
    float* out = (float*)d_out;

    __half *faN, *fbN;
    float *corr, *pool, *amax, *bmax, *c1, *c2, *x3;
    cudaGetSymbolAddress((void**)&faN,  g_faN);
    cudaGetSymbolAddress((void**)&fbN,  g_fbN);
    cudaGetSymbolAddress((void**)&corr, g_corr);
    cudaGetSymbolAddress((void**)&pool, g_pool);
    cudaGetSymbolAddress((void**)&amax, g_amax);
    cudaGetSymbolAddress((void**)&bmax, g_bmax);
    cudaGetSymbolAddress((void**)&c1,   g_c1);
    cudaGetSymbolAddress((void**)&c2,   g_c2);
    cudaGetSymbolAddress((void**)&x3,   g_x3);

    // 1) normalize + transpose to fp16 K-major
    dim3 nb(P_ / 32, B_), nt(32, 8);
    l2norm_half<<<nb, nt>>>(fA, faN);
    l2norm_half<<<nb, nt>>>(fB, fbN);

    // 2) correlation on mma.sync fp16 tensor cores
    corr_gemm_mma<<<dim3(P_ / 128, P_ / 128, B_), 256, DYNSM>>>(faN, fbN, corr);

    // 3) 4D maxpool
    const int NP = B_ * POS4_;
    maxpool_kernel<<<(NP + 255) / 256, 256>>>(corr, pool);

    // 4) mutual matching (in place)
    rowmax_kernel<<<(B_ * P2_) / 8, dim3(32, 8)>>>(pool, amax);
    colmax_kernel<<<dim3(P2_ / 64, B_), 64>>>(pool, bmax);
    mm_kernel<<<(NP + 255) / 256, 256>>>(pool, amax, bmax, pool);

    // 5) neighbourhood consensus convs
    dim3 cg(P2_, B_), cb(24, 6);
    conv4d_pk<1, 10><<<cg, cb>>>(pool, w1, b1, c1);
    conv4d_pk<10, 10><<<cg, cb>>>(c1, w2, b2, c2);
    conv4d_kernel<10, 1><<<cg, cb>>>(c2, w3, b3, x3);

    // 6) final mutual matching -> output
    rowmax_kernel<<<(B_ * P2_) / 8, dim3(32, 8)>>>(x3, amax);
    colmax_kernel<<<dim3(P2_ / 64, B_), 64>>>(x3, bmax);
    mm_kernel<<<(NP + 255) / 256, 256>>>(x3, amax, bmax, out);
}